// round 6
// baseline (speedup 1.0000x reference)
#include <cuda_runtime.h>

#define NW      10
#define DIM     1024
#define THREADS 128

typedef unsigned long long ull;

// ---------- packed f32x2 helpers ----------
__device__ __forceinline__ ull pk(float lo, float hi) {
    ull r;
    asm("mov.b64 %0, {%1, %2};" : "=l"(r)
        : "r"(__float_as_uint(lo)), "r"(__float_as_uint(hi)));
    return r;
}
__device__ __forceinline__ void upk(ull v, float& lo, float& hi) {
    unsigned a, b;
    asm("mov.b64 {%0, %1}, %2;" : "=r"(a), "=r"(b) : "l"(v));
    lo = __uint_as_float(a); hi = __uint_as_float(b);
}
__device__ __forceinline__ ull swp(ull v) {
    float lo, hi; upk(v, lo, hi); return pk(hi, lo);
}
__device__ __forceinline__ ull fma2(ull a, ull b, ull c) {
    ull d;
    asm("fma.rn.f32x2 %0, %1, %2, %3;" : "=l"(d) : "l"(a), "l"(b), "l"(c));
    return d;
}
__device__ __forceinline__ ull mul2(ull a, ull b) {
    ull d;
    asm("mul.rn.f32x2 %0, %1, %2;" : "=l"(d) : "l"(a), "l"(b));
    return d;
}

// ---------- gates (coefficients from shared memory) ----------
// Complex 2x2 on register bit kb.
__device__ __forceinline__ void cgate_reg(ull* r, const ull* g, const int kb) {
    const ull a2 = g[0], ai2 = g[1], b2 = g[2], bi2 = g[3];
    const ull c2 = g[4], ci2 = g[5], d2 = g[6], di2 = g[7];
#pragma unroll
    for (int m = 0; m < 8; m++) {
        if ((m >> kb) & 1) continue;
        const int m1 = m | (1 << kb);
        ull u = r[m], v = r[m1];
        ull us = swp(u), vs = swp(v);
        r[m]  = fma2(a2, u, fma2(ai2, us, fma2(b2, v, mul2(bi2, vs))));
        r[m1] = fma2(c2, u, fma2(ci2, us, fma2(d2, v, mul2(di2, vs))));
    }
}

// Complex 2x2 on lane bit lb via shuffle (coeff role select hoisted per gate).
__device__ __forceinline__ void cgate_shfl(ull* r, const ull* g,
                                           const int lb, const int lane) {
    const bool hi = (lane >> lb) & 1;
    const ull p2  = hi ? g[6] : g[0];
    const ull pi2 = hi ? g[7] : g[1];
    const ull q2  = hi ? g[4] : g[2];
    const ull qi2 = hi ? g[5] : g[3];
#pragma unroll
    for (int k = 0; k < 8; k++) {
        float ux, uy; upk(r[k], ux, uy);
        float vx = __shfl_xor_sync(0xffffffffu, ux, 1 << lb);
        float vy = __shfl_xor_sync(0xffffffffu, uy, 1 << lb);
        r[k] = fma2(p2, r[k],
               fma2(pi2, pk(uy, ux),
               fma2(q2, pk(vx, vy), mul2(qi2, pk(vy, vx)))));
    }
}

// Real RY on register bit kb.
__device__ __forceinline__ void rgate_reg(ull* r, const ull* g, const int kb) {
    const ull c2 = g[0], s2 = g[1], ns2 = g[2];
#pragma unroll
    for (int m = 0; m < 8; m++) {
        if ((m >> kb) & 1) continue;
        const int m1 = m | (1 << kb);
        ull u = r[m], v = r[m1];
        r[m]  = fma2(c2, u, mul2(ns2, v));
        r[m1] = fma2(c2, v, mul2(s2, u));
    }
}

// Real RY on lane bit lb via shuffle.
__device__ __forceinline__ void rgate_shfl(ull* r, const ull* g,
                                           const int lb, const int lane) {
    const bool hi = (lane >> lb) & 1;
    const ull c2 = g[0];
    const ull q2 = hi ? g[1] : g[2];   // +s / -s
#pragma unroll
    for (int k = 0; k < 8; k++) {
        float ux, uy; upk(r[k], ux, uy);
        float vx = __shfl_xor_sync(0xffffffffu, ux, 1 << lb);
        float vy = __shfl_xor_sync(0xffffffffu, uy, 1 << lb);
        r[k] = fma2(c2, r[k], mul2(q2, pk(vx, vy)));
    }
}

__global__ __launch_bounds__(THREADS, 6)
void qsa_main(const float* __restrict__ x, float* __restrict__ out,
              const int nrows,
              const float* __restrict__ rx0,
              const float* __restrict__ ry0,
              const float* __restrict__ ry1) {
    __shared__ ull   buf0[DIM];
    __shared__ ull   buf1[DIM];
    __shared__ ull   sg1[NW * 8];     // complex fused RY*RX per wire
    __shared__ ull   sg2[NW * 4];     // real RY per wire
    __shared__ float snorm[2][4];     // parity double-buffered per row iter
    __shared__ float swred[4 * NW];

    const int t    = threadIdx.x;
    const int lane = t & 31;
    const int w    = t >> 5;

    // ---- Compute gate coefficients once per CTA (fused prep) ----
    if (t < NW) {
        float cx, sx, cy, sy, cz, sz;
        sincosf(0.5f * __ldg(rx0 + t), &sx, &cx);
        sincosf(0.5f * __ldg(ry0 + t), &sy, &cy);
        sincosf(0.5f * __ldg(ry1 + t), &sz, &cz);
        // G = RY(ry0)@RX(rx0): a = cx*cy + i sx*sy ; b = -sy*cx - i sx*cy ;
        //                      c = sy*cx - i sx*cy ; d = cx*cy - i sx*sy
        float ar =  cx * cy, ai =  sx * sy;
        float br = -sy * cx, bi = -sx * cy;
        float cr =  sy * cx, ci = -sx * cy;
        float dr =  cx * cy, di = -sx * sy;
        ull* g = sg1 + t * 8;
        g[0] = pk(ar, ar);   g[1] = pk(-ai, ai);
        g[2] = pk(br, br);   g[3] = pk(-bi, bi);
        g[4] = pk(cr, cr);   g[5] = pk(-ci, ci);
        g[6] = pk(dr, dr);   g[7] = pk(-di, di);
        ull* h = sg2 + t * 4;
        h[0] = pk(cz, cz);   h[1] = pk(sz, sz);   h[2] = pk(-sz, -sz);
        h[3] = 0;
    }
    __syncthreads();

    int par = 0;
    for (int row = blockIdx.x; row < nrows; row += gridDim.x, par ^= 1) {
        // ---- Load (layout A: i = t + 128k; lane=bits0-4, warp=bits5-6, k=bits7-9)
        ull r[8];
        float ss = 0.f;
        const float* xr = x + (size_t)row * DIM;
#pragma unroll
        for (int k = 0; k < 8; k++) {
            float v = __ldg(xr + t + THREADS * k);
            r[k] = pk(v, 0.f);
            ss += v * v;
        }
#pragma unroll
        for (int o = 16; o; o >>= 1) ss += __shfl_xor_sync(0xffffffffu, ss, o);
        if (lane == 0) snorm[par][w] = ss;   // consumed by output threads post-sync4

        // ======== Layer 1 (fused complex RY*RX per wire) ========
        cgate_reg(r, sg1 + 8 * 0, 2);          // q0 <-> bit9
        cgate_reg(r, sg1 + 8 * 1, 1);          // q1 <-> bit8
        cgate_reg(r, sg1 + 8 * 2, 0);          // q2 <-> bit7
        cgate_shfl(r, sg1 + 8 * 5, 4, lane);   // q5 <-> bit4
        cgate_shfl(r, sg1 + 8 * 6, 3, lane);   // q6
        cgate_shfl(r, sg1 + 8 * 7, 2, lane);   // q7
        cgate_shfl(r, sg1 + 8 * 8, 1, lane);   // q8
        cgate_shfl(r, sg1 + 8 * 9, 0, lane);   // q9 <-> bit0

        // ---- Exchange A -> B (layout B: i = lane | (k<<5) | (w<<8)) ----
#pragma unroll
        for (int k = 0; k < 8; k++) buf0[t + THREADS * k] = r[k];
        __syncthreads();                                   // sync1
#pragma unroll
        for (int k = 0; k < 8; k++) r[k] = buf0[lane | (k << 5) | (w << 8)];

        cgate_reg(r, sg1 + 8 * 4, 0);          // q4 <-> bit5
        cgate_reg(r, sg1 + 8 * 3, 1);          // q3 <-> bit6

        // ---- CNOT ring (suffix-XOR permutation), fused with exchange B -> A ----
#pragma unroll
        for (int k = 0; k < 8; k++) {
            unsigned i = (unsigned)(lane | (k << 5) | (w << 8));
            unsigned y = i;
            y ^= y >> 1; y ^= y >> 2; y ^= y >> 4; y ^= y >> 8;
            unsigned dst = (y & 0x1FFu) | (((y ^ (i >> 9)) & 1u) << 9);
            buf1[dst] = r[k];
        }
        __syncthreads();                                   // sync2
#pragma unroll
        for (int k = 0; k < 8; k++) r[k] = buf1[t + THREADS * k];

        // ======== Layer 2 (real RY per wire) ========
        rgate_reg(r, sg2 + 4 * 0, 2);
        rgate_reg(r, sg2 + 4 * 1, 1);
        rgate_reg(r, sg2 + 4 * 2, 0);
        rgate_shfl(r, sg2 + 4 * 5, 4, lane);
        rgate_shfl(r, sg2 + 4 * 6, 3, lane);
        rgate_shfl(r, sg2 + 4 * 7, 2, lane);
        rgate_shfl(r, sg2 + 4 * 8, 1, lane);
        rgate_shfl(r, sg2 + 4 * 9, 0, lane);

        // ---- Exchange A -> B again ----
#pragma unroll
        for (int k = 0; k < 8; k++) buf0[t + THREADS * k] = r[k];
        __syncthreads();                                   // sync3
#pragma unroll
        for (int k = 0; k < 8; k++) r[k] = buf0[lane | (k << 5) | (w << 8)];

        rgate_reg(r, sg2 + 4 * 4, 0);          // q4 <-> bit5
        rgate_reg(r, sg2 + 4 * 3, 1);          // q3 <-> bit6

        // ======== <Z_j> reduction (layout B: bits5-7 = k; 8,9 = w; 0-4 = lane) ====
        float tot = 0.f, a2 = 0.f, a3 = 0.f, a4 = 0.f;
#pragma unroll
        for (int k = 0; k < 8; k++) {
            float px, py; upk(r[k], px, py);
            float p = px * px + py * py;
            tot += p;
            a4 += (k & 1) ? -p : p;   // q4 <-> bit5
            a3 += (k & 2) ? -p : p;   // q3 <-> bit6
            a2 += (k & 4) ? -p : p;   // q2 <-> bit7
        }
        // Spawning sum/difference tree over lane bits.
        float s = tot, d4, d3, d2v, d1, d0;
        {
            float n = __shfl_xor_sync(0xffffffffu, s, 16);
            d4 = (lane & 16) ? n - s : s - n; s += n;
        }
        {
            float n = __shfl_xor_sync(0xffffffffu, s, 8);
            d3 = (lane & 8) ? n - s : s - n; s += n;
            d4 += __shfl_xor_sync(0xffffffffu, d4, 8);
        }
        {
            float n = __shfl_xor_sync(0xffffffffu, s, 4);
            d2v = (lane & 4) ? n - s : s - n; s += n;
            d4 += __shfl_xor_sync(0xffffffffu, d4, 4);
            d3 += __shfl_xor_sync(0xffffffffu, d3, 4);
        }
        {
            float n = __shfl_xor_sync(0xffffffffu, s, 2);
            d1 = (lane & 2) ? n - s : s - n; s += n;
            d4 += __shfl_xor_sync(0xffffffffu, d4, 2);
            d3 += __shfl_xor_sync(0xffffffffu, d3, 2);
            d2v += __shfl_xor_sync(0xffffffffu, d2v, 2);
        }
        {
            float n = __shfl_xor_sync(0xffffffffu, s, 1);
            d0 = (lane & 1) ? n - s : s - n; s += n;
            d4 += __shfl_xor_sync(0xffffffffu, d4, 1);
            d3 += __shfl_xor_sync(0xffffffffu, d3, 1);
            d2v += __shfl_xor_sync(0xffffffffu, d2v, 1);
            d1 += __shfl_xor_sync(0xffffffffu, d1, 1);
        }
#pragma unroll
        for (int o = 16; o; o >>= 1) {
            a2 += __shfl_xor_sync(0xffffffffu, a2, o);
            a3 += __shfl_xor_sync(0xffffffffu, a3, o);
            a4 += __shfl_xor_sync(0xffffffffu, a4, o);
        }
        if (lane == 0) {
            swred[w * NW + 0] = ((w >> 1) & 1) ? -s : s;   // q0 <-> bit9 (w bit1)
            swred[w * NW + 1] = ( w       & 1) ? -s : s;   // q1 <-> bit8
            swred[w * NW + 2] = a2;
            swred[w * NW + 3] = a3;
            swred[w * NW + 4] = a4;
            swred[w * NW + 5] = d4;
            swred[w * NW + 6] = d3;
            swred[w * NW + 7] = d2v;
            swred[w * NW + 8] = d1;
            swred[w * NW + 9] = d0;
        }
        __syncthreads();                                   // sync4
        if (t < NW) {
            float sn = snorm[par][0] + snorm[par][1] + snorm[par][2] + snorm[par][3];
            float e  = swred[t] + swred[NW + t] + swred[2 * NW + t] + swred[3 * NW + t];
            out[(size_t)row * NW + t] = e / fmaxf(sn, 1e-24f);
        }
        // next iteration's snorm writes target snorm[par^1]; swred rewrites are
        // ordered behind sync3 of the next row iteration.
    }
}

extern "C" void kernel_launch(void* const* d_in, const int* in_sizes, int n_in,
                              void* d_out, int out_size) {
    const float* x   = (const float*)d_in[0];
    const float* rx0 = (const float*)d_in[1];
    const float* ry0 = (const float*)d_in[2];
    const float* ry1 = (const float*)d_in[3];
    float* out = (float*)d_out;

    int nrows = in_sizes[0] / DIM;  // 4096

    // Persistent CTAs sized to true occupancy (6 CTAs/SM x 148 SMs).
    int grid = 888;
    if (grid > nrows) grid = nrows;
    qsa_main<<<grid, THREADS>>>(x, out, nrows, rx0, ry0, ry1);
}